// round 2
// baseline (speedup 1.0000x reference)
#include <cuda_runtime.h>
#include <math.h>

// Problem dims
#define BQ   1024   // batch
#define LQ   128    // seq len
#define EQ   100    // embed dim
#define HQ   512    // hidden
#define KA   612    // 512 (h) + 100 (x)
#define LDA  640    // padded A stride (floats)
#define NG   2048   // 4 gate blocks of 512: r | z | gh_n | gi_n

// Scratch (device globals — no allocation allowed)
__device__ float g_A[2][2][BQ][LDA];   // double-buffered [h | x] per GRU, ~10.5 MB
__device__ float g_W[2][NG][KA];       // packed weights per GRU, ~10 MB
__device__ float g_bias[2][NG];
__device__ float g_G[2][BQ][NG];       // gate pre-activations, ~16.8 MB
__device__ float g_S[BQ][BQ];          // scores, 4 MB

// ---------------------------------------------------------------------------
// Pack [Whh | Wih] into gate-ordered rows:
//  rows [0,512)    : r gate, K=612  ([Whh_r | Wih_r]), bias bih+bhh
//  rows [512,1024) : z gate, K=612
//  rows [1024,1536): gh_n,   K=512  ([Whh_n | 0]),    bias bhh
//  rows [1536,2048): gi_n,   K=100  ([0 | Wih_n]),    bias bih
// ---------------------------------------------------------------------------
__global__ void pack_weights(const float* __restrict__ Wih0, const float* __restrict__ Whh0,
                             const float* __restrict__ bih0, const float* __restrict__ bhh0,
                             const float* __restrict__ Wih1, const float* __restrict__ Whh1,
                             const float* __restrict__ bih1, const float* __restrict__ bhh1) {
    const long total = 2L * NG * KA;
    for (long idx = (long)blockIdx.x * blockDim.x + threadIdx.x; idx < total;
         idx += (long)gridDim.x * blockDim.x) {
        int g   = (int)(idx / (NG * KA));
        int rem = (int)(idx % (NG * KA));
        int j = rem / KA;
        int k = rem % KA;
        const float* Wih = g ? Wih1 : Wih0;
        const float* Whh = g ? Whh1 : Whh0;
        float v;
        if (j < 1024) {
            v = (k < 512) ? Whh[j * 512 + k] : Wih[j * 100 + (k - 512)];
        } else if (j < 1536) {
            v = (k < 512) ? Whh[j * 512 + k] : 0.f;
        } else {
            v = (k >= 512) ? Wih[(j - 512) * 100 + (k - 512)] : 0.f;
        }
        g_W[g][j][k] = v;
    }
    for (int idx = blockIdx.x * blockDim.x + threadIdx.x; idx < 2 * NG;
         idx += gridDim.x * blockDim.x) {
        int g = idx / NG;
        int j = idx % NG;
        const float* bih = g ? bih1 : bih0;
        const float* bhh = g ? bhh1 : bhh0;
        float v;
        if (j < 1024)      v = bih[j] + bhh[j];
        else if (j < 1536) v = bhh[j];
        else               v = bih[j - 512];
        g_bias[g][j] = v;
    }
}

// h0 = 0, and gather x for step 0 (time t = L-1, backward direction)
__global__ void init_state(const int* __restrict__ tok0, const int* __restrict__ tok1,
                           const float* __restrict__ emb0, const float* __restrict__ emb1) {
    const int total = 2 * BQ * LDA;
    for (int idx = blockIdx.x * blockDim.x + threadIdx.x; idx < total;
         idx += gridDim.x * blockDim.x) {
        int g   = idx / (BQ * LDA);
        int rem = idx % (BQ * LDA);
        int b = rem / LDA;
        int k = rem % LDA;
        float v = 0.f;
        if (k >= 512 && k < 512 + EQ) {
            const int*   tok = g ? tok1 : tok0;
            const float* emb = g ? emb1 : emb0;
            int t = tok[b * LQ + (LQ - 1)];
            v = emb[t * EQ + (k - 512)];
        }
        g_A[0][g][b][k] = v;
    }
}

// ---------------------------------------------------------------------------
// Per-step GEMM: G[g] = A[g] (1024 x K) * W[g]^T (K x 2048) + bias
// BM=BN=64, BK=16, 256 threads, 4x4 micro-tile. K-range depends on gate region.
// ---------------------------------------------------------------------------
__global__ __launch_bounds__(256) void gru_gemm(int cur) {
    const int g  = blockIdx.z;
    const int bm = blockIdx.y;
    const int bn = blockIdx.x;
    const int n0 = bn * 64;
    const int region = n0 >> 9;                 // 0..3
    const int ks = (region == 3) ? 512 : 0;
    const int ke = (region == 2) ? 512 : KA;

    __shared__ float As[16][68];
    __shared__ float Bs[16][68];

    const int tid = threadIdx.x;
    const int tx = tid & 15;
    const int ty = tid >> 4;

    float acc[4][4];
#pragma unroll
    for (int i = 0; i < 4; i++)
#pragma unroll
        for (int j = 0; j < 4; j++) acc[i][j] = 0.f;

    const float* Abase = &g_A[cur][g][bm * 64][0];
    const float* Wbase = &g_W[g][n0][0];

    for (int k0 = ks; k0 < ke; k0 += 16) {
#pragma unroll
        for (int i = 0; i < 4; i++) {
            int e = tid + 256 * i;
            int m = e >> 4;
            int k = e & 15;
            bool ok = (k0 + k) < ke;
            As[k][m] = ok ? Abase[m * LDA + k0 + k] : 0.f;
            Bs[k][m] = ok ? Wbase[m * KA  + k0 + k] : 0.f;
        }
        __syncthreads();
#pragma unroll
        for (int kk = 0; kk < 16; kk++) {
            float4 a4 = *(const float4*)&As[kk][ty * 4];
            float4 b4 = *(const float4*)&Bs[kk][tx * 4];
            float av[4] = {a4.x, a4.y, a4.z, a4.w};
            float bv[4] = {b4.x, b4.y, b4.z, b4.w};
#pragma unroll
            for (int i = 0; i < 4; i++)
#pragma unroll
                for (int j = 0; j < 4; j++) acc[i][j] += av[i] * bv[j];
        }
        __syncthreads();
    }

    const int row = bm * 64 + ty * 4;
    const int col = n0 + tx * 4;
#pragma unroll
    for (int i = 0; i < 4; i++)
#pragma unroll
        for (int j = 0; j < 4; j++)
            g_G[g][row + i][col + j] = acc[i][j] + g_bias[g][col + j];
}

// ---------------------------------------------------------------------------
// Gates + state update; also gathers next step's embedding into A[next].
// s_next = index of the NEXT step (gather skipped when s_next == LQ).
// ---------------------------------------------------------------------------
__global__ void gru_pointwise(int cur, int s_next,
                              const int* __restrict__ tok0, const int* __restrict__ tok1,
                              const float* __restrict__ emb0, const float* __restrict__ emb1) {
    const int g = blockIdx.y;
    const int idx = blockIdx.x * blockDim.x + threadIdx.x;   // 1024*512
    const int b = idx >> 9;
    const int j = idx & 511;
    const float* Gb = &g_G[g][b][0];
    float r = 1.f / (1.f + expf(-Gb[j]));
    float z = 1.f / (1.f + expf(-Gb[512 + j]));
    float n = tanhf(Gb[1536 + j] + r * Gb[1024 + j]);
    float h = g_A[cur][g][b][j];
    float hn = (1.f - z) * n + z * h;
    const int nxt = cur ^ 1;
    g_A[nxt][g][b][j] = hn;
    if (s_next < LQ && j < EQ) {
        const int*   tok = g ? tok1 : tok0;
        const float* emb = g ? emb1 : emb0;
        int t = tok[b * LQ + (LQ - 1 - s_next)];
        g_A[nxt][g][b][512 + j] = emb[t * EQ + j];
    }
}

// ---------------------------------------------------------------------------
// S = hc @ hr^T  (1024 x 1024, K=512). Final h lives in buffer 0 (128 steps).
// ---------------------------------------------------------------------------
__global__ __launch_bounds__(256) void score_gemm() {
    const int bm = blockIdx.y;
    const int bn = blockIdx.x;
    __shared__ float As[16][68];
    __shared__ float Bs[16][68];
    const int tid = threadIdx.x;
    const int tx = tid & 15;
    const int ty = tid >> 4;

    float acc[4][4];
#pragma unroll
    for (int i = 0; i < 4; i++)
#pragma unroll
        for (int j = 0; j < 4; j++) acc[i][j] = 0.f;

    const float* Abase = &g_A[0][0][bm * 64][0];
    const float* Bbase = &g_A[0][1][bn * 64][0];

    for (int k0 = 0; k0 < HQ; k0 += 16) {
#pragma unroll
        for (int i = 0; i < 4; i++) {
            int e = tid + 256 * i;
            int m = e >> 4;
            int k = e & 15;
            As[k][m] = Abase[m * LDA + k0 + k];
            Bs[k][m] = Bbase[m * LDA + k0 + k];
        }
        __syncthreads();
#pragma unroll
        for (int kk = 0; kk < 16; kk++) {
            float4 a4 = *(const float4*)&As[kk][ty * 4];
            float4 b4 = *(const float4*)&Bs[kk][tx * 4];
            float av[4] = {a4.x, a4.y, a4.z, a4.w};
            float bv[4] = {b4.x, b4.y, b4.z, b4.w};
#pragma unroll
            for (int i = 0; i < 4; i++)
#pragma unroll
                for (int j = 0; j < 4; j++) acc[i][j] += av[i] * bv[j];
        }
        __syncthreads();
    }
    const int row = bm * 64 + ty * 4;
    const int col = bn * 64 + tx * 4;
#pragma unroll
    for (int i = 0; i < 4; i++)
#pragma unroll
        for (int j = 0; j < 4; j++) g_S[row + i][col + j] = acc[i][j];
}

__global__ void softmax_rows(float* __restrict__ out) {
    const int row = blockIdx.x;
    __shared__ float red[256];
    const float* Srow = g_S[row];

    float m = -INFINITY;
    for (int j = threadIdx.x; j < BQ; j += 256) m = fmaxf(m, Srow[j]);
    red[threadIdx.x] = m;
    __syncthreads();
    for (int off = 128; off; off >>= 1) {
        if (threadIdx.x < off) red[threadIdx.x] = fmaxf(red[threadIdx.x], red[threadIdx.x + off]);
        __syncthreads();
    }
    m = red[0];
    __syncthreads();

    float sum = 0.f;
    for (int j = threadIdx.x; j < BQ; j += 256) sum += expf(Srow[j] - m);
    red[threadIdx.x] = sum;
    __syncthreads();
    for (int off = 128; off; off >>= 1) {
        if (threadIdx.x < off) red[threadIdx.x] += red[threadIdx.x + off];
        __syncthreads();
    }
    sum = red[0];

    float inv = 1.f / sum;
    for (int j = threadIdx.x; j < BQ; j += 256) out[row * BQ + j] = expf(Srow[j] - m) * inv;
}

// ---------------------------------------------------------------------------
extern "C" void kernel_launch(void* const* d_in, const int* in_sizes, int n_in,
                              void* d_out, int out_size) {
    const int*   ctx     = (const int*)  d_in[0];
    const int*   rep     = (const int*)  d_in[1];
    const float* ctx_emb = (const float*)d_in[2];
    const float* ctx_Wih = (const float*)d_in[3];
    const float* ctx_Whh = (const float*)d_in[4];
    const float* ctx_bih = (const float*)d_in[5];
    const float* ctx_bhh = (const float*)d_in[6];
    const float* rep_emb = (const float*)d_in[7];
    const float* rep_Wih = (const float*)d_in[8];
    const float* rep_Whh = (const float*)d_in[9];
    const float* rep_bih = (const float*)d_in[10];
    const float* rep_bhh = (const float*)d_in[11];

    pack_weights<<<4096, 256>>>(ctx_Wih, ctx_Whh, ctx_bih, ctx_bhh,
                                rep_Wih, rep_Whh, rep_bih, rep_bhh);
    init_state<<<4096, 256>>>(ctx, rep, ctx_emb, rep_emb);

    for (int s = 0; s < LQ; s++) {
        int cur = s & 1;
        gru_gemm<<<dim3(32, 16, 2), 256>>>(cur);
        gru_pointwise<<<dim3(2048, 2), 256>>>(cur, s + 1, ctx, rep, ctx_emb, rep_emb);
    }

    score_gemm<<<dim3(16, 16), 256>>>();
    softmax_rows<<<BQ, 256>>>((float*)d_out);
}

// round 5
// speedup vs baseline: 2.6446x; 2.6446x over previous
#include <cuda_runtime.h>
#include <cuda_bf16.h>
#include <cstdint>
#include <math.h>

#define BQ 1024
#define LQ 128
#define EQ 100
#define HQ 512
#define KT 640          // per-term K: 512 (h) + 128 (x pad)
#define KP 1920         // 3 split terms
#define NGI 2048        // interleaved: group(16) x [32r|32z|32ghn|32gin]
#define NK_ITERS 30     // 1920 / 64

// smem layout (bytes)
#define SM_AS0 0
#define SM_AS1 32768
#define SM_BS0 65536
#define SM_BS1 81920
#define SM_CS  98304
#define CS_LD  129
#define SMEM_TOTAL (98304 + 256 * CS_LD * 4)   // 230,400 B

// ---- device scratch (no allocation allowed) ----
__device__ __align__(128) __nv_bfloat16 g_Ab[2][2][BQ][KP];   // ~15.7MB
__device__ __align__(128) __nv_bfloat16 g_Wb[2][NGI][KP];     // ~15.7MB
__device__ __align__(128) float         g_bias[2][NGI];
__device__ __align__(128) float         g_Hf[2][2][BQ][HQ];   // ~8.4MB
__device__ __align__(128) float         g_S[BQ][BQ];          // 4MB

// ---- asm helpers ----
#define LDSM4(R0,R1,R2,R3,ADDR) \
  asm volatile("ldmatrix.sync.aligned.m8n8.x4.shared.b16 {%0,%1,%2,%3},[%4];" \
    : "=r"(R0),"=r"(R1),"=r"(R2),"=r"(R3) : "r"(ADDR))

#define MMA16816(C,A0,A1,A2,A3,B0,B1) \
  asm volatile("mma.sync.aligned.m16n8k16.row.col.f32.bf16.bf16.f32 " \
    "{%0,%1,%2,%3},{%4,%5,%6,%7},{%8,%9},{%0,%1,%2,%3};" \
    : "+f"(C[0]),"+f"(C[1]),"+f"(C[2]),"+f"(C[3]) \
    : "r"(A0),"r"(A1),"r"(A2),"r"(A3),"r"(B0),"r"(B1))

#define CPASYNC16(DST,SRC) \
  asm volatile("cp.async.cg.shared.global [%0],[%1],16;" :: "r"(DST),"l"(SRC))
#define CPCOMMIT asm volatile("cp.async.commit_group;" ::: "memory")

// ---------------------------------------------------------------------------
// Pack weights into split-bf16, gate-interleaved layout.
// col n: group=n>>7, sub=(n>>5)&3, u=n&31, h=group*32+u
//   sub0: r    = [Whh_r | Wih_r], bias bih_r+bhh_r
//   sub1: z    = [Whh_z | Wih_z], bias bih_z+bhh_z
//   sub2: gh_n = [Whh_n |  0  ],  bias bhh_n
//   sub3: gi_n = [  0   | Wih_n], bias bih_n
// k' term t = k/640: t0 -> W_hi, t1 -> W_lo, t2 -> W_hi
// (A terms: t0 -> A_hi, t1 -> A_hi, t2 -> A_lo; sum = hi*hi + hi*lo + lo*hi)
// ---------------------------------------------------------------------------
__global__ void pack_weights(const float* __restrict__ Wih0, const float* __restrict__ Whh0,
                             const float* __restrict__ bih0, const float* __restrict__ bhh0,
                             const float* __restrict__ Wih1, const float* __restrict__ Whh1,
                             const float* __restrict__ bih1, const float* __restrict__ bhh1) {
    const long total = 2L * NGI * KP;
    for (long idx = (long)blockIdx.x * blockDim.x + threadIdx.x; idx < total;
         idx += (long)gridDim.x * blockDim.x) {
        int g   = (int)(idx / (NGI * (long)KP));
        int rem = (int)(idx - (long)g * NGI * KP);
        int n = rem / KP;
        int k = rem - n * KP;
        int t  = k / KT;
        int kk = k - t * KT;
        int sub = (n >> 5) & 3;
        int h   = ((n >> 7) << 5) | (n & 31);
        const float* Wih = g ? Wih1 : Wih0;
        const float* Whh = g ? Whh1 : Whh0;
        float v = 0.f;
        if (kk < HQ) {
            int gate = (sub == 0) ? 0 : (sub == 1) ? 1 : (sub == 2) ? 2 : -1;
            if (gate >= 0) v = Whh[(gate * HQ + h) * HQ + kk];
        } else {
            int e = kk - HQ;
            if (e < EQ) {
                int gate = (sub == 0) ? 0 : (sub == 1) ? 1 : (sub == 3) ? 2 : -1;
                if (gate >= 0) v = Wih[(gate * HQ + h) * EQ + e];
            }
        }
        __nv_bfloat16 hi = __float2bfloat16(v);
        __nv_bfloat16 out = (t == 1) ? __float2bfloat16(v - __bfloat162float(hi)) : hi;
        g_Wb[g][n][k] = out;
    }
    for (int idx = blockIdx.x * blockDim.x + threadIdx.x; idx < 2 * NGI;
         idx += gridDim.x * blockDim.x) {
        int g = idx / NGI;
        int n = idx - g * NGI;
        int sub = (n >> 5) & 3;
        int h   = ((n >> 7) << 5) | (n & 31);
        const float* bih = g ? bih1 : bih0;
        const float* bhh = g ? bhh1 : bhh0;
        float b;
        if (sub == 0)      b = bih[h] + bhh[h];
        else if (sub == 1) b = bih[HQ + h] + bhh[HQ + h];
        else if (sub == 2) b = bhh[2 * HQ + h];
        else               b = bih[2 * HQ + h];
        g_bias[g][n] = b;
    }
}

// Init: h=0 (fp32 + bf16 slots), x gather for step 0 (t = L-1), pads zero.
__global__ void init_state(const int* __restrict__ tok0, const int* __restrict__ tok1,
                           const float* __restrict__ emb0, const float* __restrict__ emb1) {
    const long totalA = 2L * BQ * KP;
    for (long idx = (long)blockIdx.x * blockDim.x + threadIdx.x; idx < totalA;
         idx += (long)gridDim.x * blockDim.x) {
        int g   = (int)(idx / (BQ * (long)KP));
        int rem = (int)(idx - (long)g * BQ * KP);
        int row = rem / KP;
        int k   = rem - row * KP;
        int t  = k / KT;
        int kk = k - t * KT;
        __nv_bfloat16 out = __float2bfloat16(0.f);
        if (kk >= HQ && (kk - HQ) < EQ) {
            int e = kk - HQ;
            const int*   tok = g ? tok1 : tok0;
            const float* emb = g ? emb1 : emb0;
            int ti = tok[row * LQ + (LQ - 1)];
            float v = emb[ti * EQ + e];
            __nv_bfloat16 hi = __float2bfloat16(v);
            out = (t == 2) ? __float2bfloat16(v - __bfloat162float(hi)) : hi;
        }
        g_Ab[0][g][row][k] = out;
    }
    const int totalH = 2 * BQ * HQ;
    for (int idx = blockIdx.x * blockDim.x + threadIdx.x; idx < totalH;
         idx += gridDim.x * blockDim.x) {
        int g   = idx / (BQ * HQ);
        int rem = idx - g * BQ * HQ;
        g_Hf[0][g][rem / HQ][rem % HQ] = 0.f;
    }
}

// ---------------------------------------------------------------------------
// Fused GRU step: C[256x128] = A'[256x1920] @ W'^T tile, epilogue does gates,
// writes h (fp32 + split bf16) and gathers next embedding slice.
// grid: (4 m-tiles, 16 groups, 2 GRUs), 512 threads.
// ---------------------------------------------------------------------------
__global__ __launch_bounds__(512, 1) void gru_step(int cur, int s_next,
        const int* __restrict__ tok0, const int* __restrict__ tok1,
        const float* __restrict__ emb0, const float* __restrict__ emb1) {
    extern __shared__ char smem[];
    const uint32_t sbase = (uint32_t)__cvta_generic_to_shared(smem);
    const int g     = blockIdx.z;
    const int m0    = blockIdx.x * 256;
    const int group = blockIdx.y;
    const int n0    = group * 128;
    const int nxt   = cur ^ 1;
    const int tid   = threadIdx.x;
    const int lane  = tid & 31;
    const int warp  = tid >> 5;
    const int wm    = (warp >> 1) << 5;   // 0..224
    const int wn    = (warp & 1) << 6;    // 0 or 64

    const __nv_bfloat16* gA = &g_Ab[cur][g][m0][0];
    const __nv_bfloat16* gB = &g_Wb[g][n0][0];

    // per-thread load descriptors (k0 added at issue)
    uint32_t aDstOff[4]; const __nv_bfloat16* aSrcP[4];
#pragma unroll
    for (int p = 0; p < 4; p++) {
        int unit = tid + 512 * p;        // 2048 units: 256 rows x 8
        int r = unit >> 3, c = unit & 7;
        aDstOff[p] = (uint32_t)(r * 128 + ((c ^ (r & 7)) << 4));
        aSrcP[p] = gA + r * KP + c * 8;
    }
    uint32_t bDstOff[2]; const __nv_bfloat16* bSrcP[2];
#pragma unroll
    for (int p = 0; p < 2; p++) {
        int unit = tid + 512 * p;        // 1024 units: 128 rows x 8
        int r = unit >> 3, c = unit & 7;
        bDstOff[p] = (uint32_t)(r * 128 + ((c ^ (r & 7)) << 4));
        bSrcP[p] = gB + r * KP + c * 8;
    }

    float acc[2][8][4];
#pragma unroll
    for (int mi = 0; mi < 2; mi++)
#pragma unroll
        for (int ni = 0; ni < 8; ni++)
#pragma unroll
            for (int q = 0; q < 4; q++) acc[mi][ni][q] = 0.f;

    // prologue: stage iters 0 and 1
#pragma unroll
    for (int i0 = 0; i0 < 2; i0++) {
        uint32_t aB = sbase + (i0 ? SM_AS1 : SM_AS0);
        uint32_t bB = sbase + (i0 ? SM_BS1 : SM_BS0);
        int k0 = i0 * 64;
#pragma unroll
        for (int p = 0; p < 4; p++) CPASYNC16(aB + aDstOff[p], aSrcP[p] + k0);
#pragma unroll
        for (int p = 0; p < 2; p++) CPASYNC16(bB + bDstOff[p], bSrcP[p] + k0);
        CPCOMMIT;
    }

    for (int i = 0; i < NK_ITERS; i++) {
        if (i < NK_ITERS - 2) asm volatile("cp.async.wait_group 1;" ::: "memory");
        else                  asm volatile("cp.async.wait_group 0;" ::: "memory");
        __syncthreads();

        const int buf = i & 1;
        const uint32_t aB = sbase + (buf ? SM_AS1 : SM_AS0);
        const uint32_t bB = sbase + (buf ? SM_BS1 : SM_BS0);

#pragma unroll
        for (int kc = 0; kc < 4; kc++) {
            uint32_t a[2][4];
#pragma unroll
            for (int mi = 0; mi < 2; mi++) {
                int rrow = wm + mi * 16 + (lane & 15);
                int uc = kc * 2 + (lane >> 4);
                uint32_t addr = aB + (uint32_t)(rrow * 128 + ((uc ^ (rrow & 7)) << 4));
                LDSM4(a[mi][0], a[mi][1], a[mi][2], a[mi][3], addr);
            }
            uint32_t b[4][4];
#pragma unroll
            for (int j = 0; j < 4; j++) {
                int rrow = wn + 16 * j + (lane & 7) + ((lane >> 4) << 3);
                int uc = kc * 2 + ((lane >> 3) & 1);
                uint32_t addr = bB + (uint32_t)(rrow * 128 + ((uc ^ (rrow & 7)) << 4));
                LDSM4(b[j][0], b[j][1], b[j][2], b[j][3], addr);
            }
#pragma unroll
            for (int mi = 0; mi < 2; mi++)
#pragma unroll
                for (int ni = 0; ni < 8; ni++) {
                    int j = ni >> 1, hh = (ni & 1) << 1;
                    MMA16816(acc[mi][ni], a[mi][0], a[mi][1], a[mi][2], a[mi][3],
                             b[j][hh], b[j][hh + 1]);
                }
        }
        __syncthreads();

        if (i + 2 < NK_ITERS) {
            int k0 = (i + 2) * 64;
#pragma unroll
            for (int p = 0; p < 4; p++) CPASYNC16(aB + aDstOff[p], aSrcP[p] + k0);
#pragma unroll
            for (int p = 0; p < 2; p++) CPASYNC16(bB + bDstOff[p], bSrcP[p] + k0);
            CPCOMMIT;
        }
    }

    // stage C to smem
    float* Cs = (float*)(smem + SM_CS);
#pragma unroll
    for (int mi = 0; mi < 2; mi++)
#pragma unroll
        for (int ni = 0; ni < 8; ni++) {
            int row = wm + mi * 16 + (lane >> 2);
            int col = wn + ni * 8 + ((lane & 3) << 1);
            Cs[row * CS_LD + col]           = acc[mi][ni][0];
            Cs[row * CS_LD + col + 1]       = acc[mi][ni][1];
            Cs[(row + 8) * CS_LD + col]     = acc[mi][ni][2];
            Cs[(row + 8) * CS_LD + col + 1] = acc[mi][ni][3];
        }
    __syncthreads();

    // pointwise epilogue: 256 rows x 32 h-units
    const float* bias = &g_bias[g][n0];
#pragma unroll 4
    for (int p = 0; p < 16; p++) {
        int idx = tid + (p << 9);
        int r = idx >> 5, u = idx & 31;
        float rp = Cs[r * CS_LD + u]      + bias[u];
        float zp = Cs[r * CS_LD + 32 + u] + bias[32 + u];
        float gn = Cs[r * CS_LD + 64 + u] + bias[64 + u];
        float gi = Cs[r * CS_LD + 96 + u] + bias[96 + u];
        float rr = 1.f / (1.f + __expf(-rp));
        float zz = 1.f / (1.f + __expf(-zp));
        float pre = gi + rr * gn;
        float ex = __expf(-2.f * fabsf(pre));
        float nn = copysignf((1.f - ex) / (1.f + ex), pre);
        int R = m0 + r;
        int h = (group << 5) + u;
        float ho = g_Hf[cur][g][R][h];
        float hn = (1.f - zz) * nn + zz * ho;
        g_Hf[nxt][g][R][h] = hn;
        __nv_bfloat16 hi = __float2bfloat16(hn);
        __nv_bfloat16 lo = __float2bfloat16(hn - __bfloat162float(hi));
        g_Ab[nxt][g][R][h]          = hi;
        g_Ab[nxt][g][R][KT + h]     = hi;
        g_Ab[nxt][g][R][2 * KT + h] = lo;
    }

    // embedding gather for next step: this CTA handles 16 of its 256 rows
    if (s_next < LQ) {
        const int*   tok = g ? tok1 : tok0;
        const float* emb = g ? emb1 : emb0;
        int rbase = m0 + group * 16;
        for (int idx = tid; idx < 16 * EQ; idx += 512) {
            int r = idx / EQ, e = idx - r * EQ;
            int R = rbase + r;
            int ti = tok[R * LQ + (LQ - 1 - s_next)];
            float v = emb[ti * EQ + e];
            __nv_bfloat16 hi = __float2bfloat16(v);
            __nv_bfloat16 lo = __float2bfloat16(v - __bfloat162float(hi));
            g_Ab[nxt][g][R][HQ + e]          = hi;
            g_Ab[nxt][g][R][KT + HQ + e]     = hi;
            g_Ab[nxt][g][R][2 * KT + HQ + e] = lo;
        }
    }
}

// ---------------------------------------------------------------------------
// S = hc @ hr^T (fp32, K=512) + row softmax
// ---------------------------------------------------------------------------
__global__ __launch_bounds__(256) void score_gemm() {
    const int bm = blockIdx.y;
    const int bn = blockIdx.x;
    __shared__ float As[16][68];
    __shared__ float Bs[16][68];
    const int tid = threadIdx.x;
    const int tx = tid & 15;
    const int ty = tid >> 4;

    float acc[4][4];
#pragma unroll
    for (int i = 0; i < 4; i++)
#pragma unroll
        for (int j = 0; j < 4; j++) acc[i][j] = 0.f;

    const float* Abase = &g_Hf[0][0][bm * 64][0];
    const float* Bbase = &g_Hf[0][1][bn * 64][0];

    for (int k0 = 0; k0 < HQ; k0 += 16) {
#pragma unroll
        for (int i = 0; i < 4; i++) {
            int e = tid + 256 * i;
            int m = e >> 4;
            int k = e & 15;
            As[k][m] = Abase[m * HQ + k0 + k];
            Bs[k][m] = Bbase[m * HQ + k0 + k];
        }
        __syncthreads();
#pragma unroll
        for (int kk = 0; kk < 16; kk++) {
            float4 a4 = *(const float4*)&As[kk][ty * 4];
            float4 b4 = *(const float4*)&Bs[kk][tx * 4];
            float av[4] = {a4.x, a4.y, a4.z, a4.w};
            float bv[4] = {b4.x, b4.y, b4.z, b4.w};
#pragma unroll
            for (int i = 0; i < 4; i++)
#pragma unroll
                for (int j = 0; j < 4; j++) acc[i][j] += av[i] * bv[j];
        }
        __syncthreads();
    }
    const int row = bm * 64 + ty * 4;
    const int col = bn * 64 + tx * 4;
#pragma unroll
    for (int i = 0; i < 4; i++)
#pragma unroll
        for (int j = 0; j < 4; j++) g_S[row + i][col + j] = acc[i][j];
}

__global__ void softmax_rows(float* __restrict__ out) {
    const int row = blockIdx.x;
    __shared__ float red[256];
    const float* Srow = g_S[row];

    float m = -INFINITY;
    for (int j = threadIdx.x; j < BQ; j += 256) m = fmaxf(m, Srow[j]);
    red[threadIdx.x] = m;
    __syncthreads();
    for (int off = 128; off; off >>= 1) {
        if (threadIdx.x < off) red[threadIdx.x] = fmaxf(red[threadIdx.x], red[threadIdx.x + off]);
        __syncthreads();
    }
    m = red[0];
    __syncthreads();

    float sum = 0.f;
    for (int j = threadIdx.x; j < BQ; j += 256) sum += expf(Srow[j] - m);
    red[threadIdx.x] = sum;
    __syncthreads();
    for (int off = 128; off; off >>= 1) {
        if (threadIdx.x < off) red[threadIdx.x] += red[threadIdx.x + off];
        __syncthreads();
    }
    sum = red[0];

    float inv = 1.f / sum;
    for (int j = threadIdx.x; j < BQ; j += 256) out[row * BQ + j] = expf(Srow[j] - m) * inv;
}

// ---------------------------------------------------------------------------
extern "C" void kernel_launch(void* const* d_in, const int* in_sizes, int n_in,
                              void* d_out, int out_size) {
    const int*   ctx     = (const int*)  d_in[0];
    const int*   rep     = (const int*)  d_in[1];
    const float* ctx_emb = (const float*)d_in[2];
    const float* ctx_Wih = (const float*)d_in[3];
    const float* ctx_Whh = (const float*)d_in[4];
    const float* ctx_bih = (const float*)d_in[5];
    const float* ctx_bhh = (const float*)d_in[6];
    const float* rep_emb = (const float*)d_in[7];
    const float* rep_Wih = (const float*)d_in[8];
    const float* rep_Whh = (const float*)d_in[9];
    const float* rep_bih = (const float*)d_in[10];
    const float* rep_bhh = (const float*)d_in[11];

    cudaFuncSetAttribute(gru_step, cudaFuncAttributeMaxDynamicSharedMemorySize, SMEM_TOTAL);

    pack_weights<<<8192, 256>>>(ctx_Wih, ctx_Whh, ctx_bih, ctx_bhh,
                                rep_Wih, rep_Whh, rep_bih, rep_bhh);
    init_state<<<8192, 256>>>(ctx, rep, ctx_emb, rep_emb);

    for (int s = 0; s < LQ; s++) {
        int cur = s & 1;
        gru_step<<<dim3(4, 16, 2), 512, SMEM_TOTAL>>>(cur, s + 1, ctx, rep, ctx_emb, rep_emb);
    }

    score_gemm<<<dim3(16, 16), 256>>>();
    softmax_rows<<<BQ, 256>>>((float*)d_out);
}

// round 6
// speedup vs baseline: 4.0306x; 1.5241x over previous
#include <cuda_runtime.h>
#include <cuda_bf16.h>
#include <cstdint>
#include <math.h>

#define BQ 1024
#define LQ 128
#define EQ 100
#define HQ 512
#define KT 640          // per-term K: 512 (h) + 128 (x pad)
#define KP 1280         // 2 split terms: A=(hi,lo) x W=(hi,hi)  => A*W_hi
#define NGI 2048        // 32 wgroups x 64 cols; col c: ni=c>>3,j=c&7,gate=ni>>1,u=((ni&1)<<3)|j
#define NK_ITERS 20     // 1280 / 64

// smem: 4 stages x (A 32KB + B 16KB)
#define STG_STRIDE 49152
#define SMEM_TOTAL (4 * STG_STRIDE)   // 196,608 B

// ---- device scratch ----
__device__ __align__(128) __nv_bfloat16 g_Ab[2][2][BQ][KP];   // ~10.5MB
__device__ __align__(128) __nv_bfloat16 g_Wb[2][NGI][KP];     // ~10.5MB
__device__ __align__(128) float         g_bias[2][NGI];
__device__ __align__(128) float         g_Hf[2][2][BQ][HQ];   // ~8.4MB
__device__ __align__(128) float         g_S[BQ][BQ];          // 4MB

// ---- asm helpers ----
#define LDSM4(R0,R1,R2,R3,ADDR) \
  asm volatile("ldmatrix.sync.aligned.m8n8.x4.shared.b16 {%0,%1,%2,%3},[%4];" \
    : "=r"(R0),"=r"(R1),"=r"(R2),"=r"(R3) : "r"(ADDR))

#define MMA16816(C,A0,A1,A2,A3,B0,B1) \
  asm volatile("mma.sync.aligned.m16n8k16.row.col.f32.bf16.bf16.f32 " \
    "{%0,%1,%2,%3},{%4,%5,%6,%7},{%8,%9},{%0,%1,%2,%3};" \
    : "+f"(C[0]),"+f"(C[1]),"+f"(C[2]),"+f"(C[3]) \
    : "r"(A0),"r"(A1),"r"(A2),"r"(A3),"r"(B0),"r"(B1))

#define CPASYNC16(DST,SRC) \
  asm volatile("cp.async.cg.shared.global [%0],[%1],16;" :: "r"(DST),"l"(SRC))
#define CPCOMMIT asm volatile("cp.async.commit_group;" ::: "memory")

// ---------------------------------------------------------------------------
// Pack weights. Output col n: wgrp=n>>6, c=n&63, ni=c>>3, j=c&7,
// gate=ni>>1 (0=r,1=z,2=gh_n,3=gi_n), u=((ni&1)<<3)|j, h=wgrp*16+u.
// Both k-terms hold W_hi (A carries the hi/lo split).
//   gate0 r   : [Whh_r | Wih_r], bias bih_r+bhh_r
//   gate1 z   : [Whh_z | Wih_z], bias bih_z+bhh_z
//   gate2 gh_n: [Whh_n |  0  ],  bias bhh_n
//   gate3 gi_n: [  0   | Wih_n], bias bih_n
// ---------------------------------------------------------------------------
__global__ void pack_weights(const float* __restrict__ Wih0, const float* __restrict__ Whh0,
                             const float* __restrict__ bih0, const float* __restrict__ bhh0,
                             const float* __restrict__ Wih1, const float* __restrict__ Whh1,
                             const float* __restrict__ bih1, const float* __restrict__ bhh1) {
    const long total = 2L * NGI * KP;
    for (long idx = (long)blockIdx.x * blockDim.x + threadIdx.x; idx < total;
         idx += (long)gridDim.x * blockDim.x) {
        int g   = (int)(idx / (NGI * (long)KP));
        int rem = (int)(idx - (long)g * NGI * KP);
        int n = rem / KP;
        int k = rem - n * KP;
        int kk = (k >= KT) ? (k - KT) : k;
        int wgrp = n >> 6;
        int c = n & 63;
        int ni = c >> 3;
        int j = c & 7;
        int gate = ni >> 1;
        int u = ((ni & 1) << 3) | j;
        int h = wgrp * 16 + u;
        const float* Wih = g ? Wih1 : Wih0;
        const float* Whh = g ? Whh1 : Whh0;
        float v = 0.f;
        if (kk < HQ) {
            if (gate == 0)      v = Whh[(0 * HQ + h) * HQ + kk];
            else if (gate == 1) v = Whh[(1 * HQ + h) * HQ + kk];
            else if (gate == 2) v = Whh[(2 * HQ + h) * HQ + kk];
        } else {
            int e = kk - HQ;
            if (e < EQ) {
                if (gate == 0)      v = Wih[(0 * HQ + h) * EQ + e];
                else if (gate == 1) v = Wih[(1 * HQ + h) * EQ + e];
                else if (gate == 3) v = Wih[(2 * HQ + h) * EQ + e];
            }
        }
        g_Wb[g][n][k] = __float2bfloat16(v);
    }
    for (int idx = blockIdx.x * blockDim.x + threadIdx.x; idx < 2 * NGI;
         idx += gridDim.x * blockDim.x) {
        int g = idx / NGI;
        int n = idx - g * NGI;
        int wgrp = n >> 6;
        int c = n & 63;
        int ni = c >> 3;
        int gate = ni >> 1;
        int u = ((ni & 1) << 3) | (c & 7);
        int h = wgrp * 16 + u;
        const float* bih = g ? bih1 : bih0;
        const float* bhh = g ? bhh1 : bhh0;
        float b;
        if (gate == 0)      b = bih[h] + bhh[h];
        else if (gate == 1) b = bih[HQ + h] + bhh[HQ + h];
        else if (gate == 2) b = bhh[2 * HQ + h];
        else                b = bih[2 * HQ + h];
        g_bias[g][n] = b;
    }
}

// Init: h=0, x gather for step 0 (t = L-1). A terms: t0=hi, t1=lo.
__global__ void init_state(const int* __restrict__ tok0, const int* __restrict__ tok1,
                           const float* __restrict__ emb0, const float* __restrict__ emb1) {
    const long totalA = 2L * BQ * KP;
    for (long idx = (long)blockIdx.x * blockDim.x + threadIdx.x; idx < totalA;
         idx += (long)gridDim.x * blockDim.x) {
        int g   = (int)(idx / (BQ * (long)KP));
        int rem = (int)(idx - (long)g * BQ * KP);
        int row = rem / KP;
        int k   = rem - row * KP;
        int t  = (k >= KT) ? 1 : 0;
        int kk = k - t * KT;
        __nv_bfloat16 out = __float2bfloat16(0.f);
        if (kk >= HQ && (kk - HQ) < EQ) {
            int e = kk - HQ;
            const int*   tok = g ? tok1 : tok0;
            const float* emb = g ? emb1 : emb0;
            int ti = tok[row * LQ + (LQ - 1)];
            float v = emb[ti * EQ + e];
            __nv_bfloat16 hi = __float2bfloat16(v);
            out = t ? __float2bfloat16(v - __bfloat162float(hi)) : hi;
        }
        g_Ab[0][g][row][k] = out;
    }
    const int totalH = 2 * BQ * HQ;
    for (int idx = blockIdx.x * blockDim.x + threadIdx.x; idx < totalH;
         idx += gridDim.x * blockDim.x) {
        int g   = idx / (BQ * HQ);
        int rem = idx - g * BQ * HQ;
        g_Hf[0][g][rem / HQ][rem % HQ] = 0.f;
    }
}

// ---------------------------------------------------------------------------
// Fused GRU step. CTA tile 256x128, K'=1280, 4-stage cp.async pipeline,
// in-register gate epilogue. grid (4,16,2) x 512 threads.
// ---------------------------------------------------------------------------
__global__ __launch_bounds__(512, 1) void gru_step(int cur, int s_next,
        const int* __restrict__ tok0, const int* __restrict__ tok1,
        const float* __restrict__ emb0, const float* __restrict__ emb1) {
    extern __shared__ char smem[];
    const uint32_t sbase = (uint32_t)__cvta_generic_to_shared(smem);
    const int g     = blockIdx.z;
    const int m0    = blockIdx.x * 256;
    const int group = blockIdx.y;
    const int n0    = group * 128;
    const int nxt   = cur ^ 1;
    const int tid   = threadIdx.x;
    const int lane  = tid & 31;
    const int warp  = tid >> 5;
    const int wm    = (warp >> 1) << 5;   // 0..224
    const int wn    = (warp & 1) << 6;    // 0 or 64

    const __nv_bfloat16* gA = &g_Ab[cur][g][m0][0];
    const __nv_bfloat16* gB = &g_Wb[g][n0][0];

    uint32_t aDstOff[4]; const __nv_bfloat16* aSrcP[4];
#pragma unroll
    for (int p = 0; p < 4; p++) {
        int unit = tid + 512 * p;        // 2048 units: 256 rows x 8
        int r = unit >> 3, c = unit & 7;
        aDstOff[p] = (uint32_t)(r * 128 + ((c ^ (r & 7)) << 4));
        aSrcP[p] = gA + r * KP + c * 8;
    }
    uint32_t bDstOff[2]; const __nv_bfloat16* bSrcP[2];
#pragma unroll
    for (int p = 0; p < 2; p++) {
        int unit = tid + 512 * p;        // 1024 units: 128 rows x 8
        int r = unit >> 3, c = unit & 7;
        bDstOff[p] = (uint32_t)(r * 128 + ((c ^ (r & 7)) << 4));
        bSrcP[p] = gB + r * KP + c * 8;
    }

    float acc[2][8][4];
#pragma unroll
    for (int mi = 0; mi < 2; mi++)
#pragma unroll
        for (int ni = 0; ni < 8; ni++)
#pragma unroll
            for (int q = 0; q < 4; q++) acc[mi][ni][q] = 0.f;

    // prologue: stage k-iters 0,1,2
#pragma unroll
    for (int i0 = 0; i0 < 3; i0++) {
        uint32_t aB = sbase + i0 * STG_STRIDE;
        uint32_t bB = aB + 32768;
        int k0 = i0 * 64;
#pragma unroll
        for (int p = 0; p < 4; p++) CPASYNC16(aB + aDstOff[p], aSrcP[p] + k0);
#pragma unroll
        for (int p = 0; p < 2; p++) CPASYNC16(bB + bDstOff[p], bSrcP[p] + k0);
        CPCOMMIT;
    }

    for (int i = 0; i < NK_ITERS; i++) {
        if (i < NK_ITERS - 2)       asm volatile("cp.async.wait_group 2;" ::: "memory");
        else if (i == NK_ITERS - 2) asm volatile("cp.async.wait_group 1;" ::: "memory");
        else                        asm volatile("cp.async.wait_group 0;" ::: "memory");
        __syncthreads();

        // issue k-iter i+3 into buffer (i+3)&3 (read last at iter i-1; safe after sync)
        if (i + 3 < NK_ITERS) {
            uint32_t aB = sbase + ((i + 3) & 3) * STG_STRIDE;
            uint32_t bB = aB + 32768;
            int k0 = (i + 3) * 64;
#pragma unroll
            for (int p = 0; p < 4; p++) CPASYNC16(aB + aDstOff[p], aSrcP[p] + k0);
#pragma unroll
            for (int p = 0; p < 2; p++) CPASYNC16(bB + bDstOff[p], bSrcP[p] + k0);
            CPCOMMIT;
        }

        const uint32_t aB = sbase + (i & 3) * STG_STRIDE;
        const uint32_t bB = aB + 32768;

#pragma unroll
        for (int kc = 0; kc < 4; kc++) {
            uint32_t a[2][4];
#pragma unroll
            for (int mi = 0; mi < 2; mi++) {
                int rrow = wm + mi * 16 + (lane & 15);
                int uc = kc * 2 + (lane >> 4);
                uint32_t addr = aB + (uint32_t)(rrow * 128 + ((uc ^ (rrow & 7)) << 4));
                LDSM4(a[mi][0], a[mi][1], a[mi][2], a[mi][3], addr);
            }
            uint32_t b[4][4];
#pragma unroll
            for (int j = 0; j < 4; j++) {
                int rrow = wn + 16 * j + (lane & 7) + ((lane >> 4) << 3);
                int uc = kc * 2 + ((lane >> 3) & 1);
                uint32_t addr = bB + (uint32_t)(rrow * 128 + ((uc ^ (rrow & 7)) << 4));
                LDSM4(b[j][0], b[j][1], b[j][2], b[j][3], addr);
            }
#pragma unroll
            for (int mi = 0; mi < 2; mi++)
#pragma unroll
                for (int ni = 0; ni < 8; ni++) {
                    int j = ni >> 1, hh = (ni & 1) << 1;
                    MMA16816(acc[mi][ni], a[mi][0], a[mi][1], a[mi][2], a[mi][3],
                             b[j][hh], b[j][hh + 1]);
                }
        }
    }

    // ---- in-register gate epilogue ----
    // acc[mi][ni][q]: row = wm + mi*16 + (lane>>2) + (q>=2)*8
    //                 col = wn + ni*8 + (lane&3)*2 + (q&1)
    // gate = ni>>1, s = ni&1, u = s*8 + (lane&3)*2 + (q&1)
    const int wgrp = group * 2 + (warp & 1);          // 0..31
    const float* bias = &g_bias[g][n0 + wn];
#pragma unroll
    for (int mi = 0; mi < 2; mi++)
#pragma unroll
        for (int s = 0; s < 2; s++)
#pragma unroll
            for (int qh = 0; qh < 2; qh++) {
                const int R = m0 + wm + mi * 16 + (lane >> 2) + qh * 8;
                const int jb = (lane & 3) * 2;
                const int hb = wgrp * 16 + s * 8 + jb;   // even
                float hn2[2];
#pragma unroll
                for (int qp = 0; qp < 2; qp++) {
                    const int q = qh * 2 + qp;
                    const int j = jb + qp;
                    float rp = acc[mi][0 + s][q] + bias[(0 + s) * 8 + j];
                    float zp = acc[mi][2 + s][q] + bias[(2 + s) * 8 + j];
                    float gn = acc[mi][4 + s][q] + bias[(4 + s) * 8 + j];
                    float gi = acc[mi][6 + s][q] + bias[(6 + s) * 8 + j];
                    float rr = 1.f / (1.f + __expf(-rp));
                    float zz = 1.f / (1.f + __expf(-zp));
                    float pre = gi + rr * gn;
                    float ex = __expf(-2.f * fabsf(pre));
                    float nn = copysignf((1.f - ex) / (1.f + ex), pre);
                    float ho = g_Hf[cur][g][R][hb + qp];
                    hn2[qp] = (1.f - zz) * nn + zz * ho;
                }
                g_Hf[nxt][g][R][hb]     = hn2[0];
                g_Hf[nxt][g][R][hb + 1] = hn2[1];
                __nv_bfloat16 h0 = __float2bfloat16(hn2[0]);
                __nv_bfloat16 h1 = __float2bfloat16(hn2[1]);
                __nv_bfloat162 hi2; hi2.x = h0; hi2.y = h1;
                __nv_bfloat162 lo2;
                lo2.x = __float2bfloat16(hn2[0] - __bfloat162float(h0));
                lo2.y = __float2bfloat16(hn2[1] - __bfloat162float(h1));
                *(__nv_bfloat162*)&g_Ab[nxt][g][R][hb]      = hi2;
                *(__nv_bfloat162*)&g_Ab[nxt][g][R][KT + hb] = lo2;
            }

    // embedding gather for next step: this CTA handles 16 of its 256 rows
    if (s_next < LQ) {
        const int*   tok = g ? tok1 : tok0;
        const float* emb = g ? emb1 : emb0;
        int rbase = m0 + group * 16;
        for (int idx = tid; idx < 16 * EQ; idx += 512) {
            int r = idx / EQ, e = idx - r * EQ;
            int R = rbase + r;
            int ti = tok[R * LQ + (LQ - 1 - s_next)];
            float v = emb[ti * EQ + e];
            __nv_bfloat16 hi = __float2bfloat16(v);
            __nv_bfloat16 lo = __float2bfloat16(v - __bfloat162float(hi));
            g_Ab[nxt][g][R][HQ + e]      = hi;
            g_Ab[nxt][g][R][KT + HQ + e] = lo;
        }
    }
}

// ---------------------------------------------------------------------------
// S = hc @ hr^T (fp32, K=512) + row softmax
// ---------------------------------------------------------------------------
__global__ __launch_bounds__(256) void score_gemm() {
    const int bm = blockIdx.y;
    const int bn = blockIdx.x;
    __shared__ float As[16][68];
    __shared__ float Bs[16][68];
    const int tid = threadIdx.x;
    const int tx = tid & 15;
    const int ty = tid >> 4;

    float acc[4][4];
#pragma unroll
    for (int i = 0; i < 4; i++)
#pragma unroll
        for (int j = 0; j < 4; j++) acc[i][j] = 0.f;

    const float* Abase = &g_Hf[0][0][bm * 64][0];
    const float* Bbase = &g_Hf[0][1][bn * 64][0];

    for (int k0 = 0; k0 < HQ; k0 += 16) {
#pragma unroll
        for (int i = 0; i < 4; i++) {
            int e = tid + 256 * i;
            int m = e >> 4;
            int k = e & 15;
            As[k][m] = Abase[m * HQ + k0 + k];
            Bs[k][m] = Bbase[m * HQ + k0 + k];
        }
        __syncthreads();
#pragma unroll
        for (int kk = 0; kk < 16; kk++) {
            float4 a4 = *(const float4*)&As[kk][ty * 4];
            float4 b4 = *(const float4*)&Bs[kk][tx * 4];
            float av[4] = {a4.x, a4.y, a4.z, a4.w};
            float bv[4] = {b4.x, b4.y, b4.z, b4.w};
#pragma unroll
            for (int i = 0; i < 4; i++)
#pragma unroll
                for (int j = 0; j < 4; j++) acc[i][j] += av[i] * bv[j];
        }
        __syncthreads();
    }
    const int row = bm * 64 + ty * 4;
    const int col = bn * 64 + tx * 4;
#pragma unroll
    for (int i = 0; i < 4; i++)
#pragma unroll
        for (int j = 0; j < 4; j++) g_S[row + i][col + j] = acc[i][j];
}

__global__ void softmax_rows(float* __restrict__ out) {
    const int row = blockIdx.x;
    __shared__ float red[256];
    const float* Srow = g_S[row];

    float m = -INFINITY;
    for (int j = threadIdx.x; j < BQ; j += 256) m = fmaxf(m, Srow[j]);
    red[threadIdx.x] = m;
    __syncthreads();
    for (int off = 128; off; off >>= 1) {
        if (threadIdx.x < off) red[threadIdx.x] = fmaxf(red[threadIdx.x], red[threadIdx.x + off]);
        __syncthreads();
    }
    m = red[0];
    __syncthreads();

    float sum = 0.f;
    for (int j = threadIdx.x; j < BQ; j += 256) sum += expf(Srow[j] - m);
    red[threadIdx.x] = sum;
    __syncthreads();
    for (int off = 128; off; off >>= 1) {
        if (threadIdx.x < off) red[threadIdx.x] += red[threadIdx.x + off];
        __syncthreads();
    }
    sum = red[0];

    float inv = 1.f / sum;
    for (int j = threadIdx.x; j < BQ; j += 256) out[row * BQ + j] = expf(Srow[j] - m) * inv;
}

// ---------------------------------------------------------------------------
extern "C" void kernel_launch(void* const* d_in, const int* in_sizes, int n_in,
                              void* d_out, int out_size) {
    const int*   ctx     = (const int*)  d_in[0];
    const int*   rep     = (const int*)  d_in[1];
    const float* ctx_emb = (const float*)d_in[2];
    const float* ctx_Wih = (const float*)d_in[3];
    const float* ctx_Whh = (const float*)d_in[4];
    const float* ctx_bih = (const float*)d_in[5];
    const float* ctx_bhh = (const float*)d_in[6];
    const float* rep_emb = (const float*)d_in[7];
    const float* rep_Wih = (const float*)d_in[8];
    const float* rep_Whh = (const float*)d_in[9];
    const float* rep_bih = (const float*)d_in[10];
    const float* rep_bhh = (const float*)d_in[11];

    cudaFuncSetAttribute(gru_step, cudaFuncAttributeMaxDynamicSharedMemorySize, SMEM_TOTAL);

    pack_weights<<<4096, 256>>>(ctx_Wih, ctx_Whh, ctx_bih, ctx_bhh,
                                rep_Wih, rep_Whh, rep_bih, rep_bhh);
    init_state<<<4096, 256>>>(ctx, rep, ctx_emb, rep_emb);

    for (int s = 0; s < LQ; s++) {
        int cur = s & 1;
        gru_step<<<dim3(4, 16, 2), 512, SMEM_TOTAL>>>(cur, s + 1, ctx, rep, ctx_emb, rep_emb);
    }

    score_gemm<<<dim3(16, 16), 256>>>();
    softmax_rows<<<BQ, 256>>>((float*)d_out);
}

// round 8
// speedup vs baseline: 4.3603x; 1.0818x over previous
#include <cuda_runtime.h>
#include <cuda_bf16.h>
#include <cstdint>
#include <math.h>

#define BQ 1024
#define LQ 128
#define EQ 100
#define HQ 512
#define KT 640          // per-term K: 512 (h) + 128 (x pad)
#define KP 1280         // 2 split terms: A=(hi,lo) x W=(hi,hi)  => A*W_hi
#define NGI 2048        // 32 wgroups x 64 cols
#define NK_ITERS 20     // 1280 / 64

// smem: 4 stages x (A 32KB + B 16KB) + mbarriers
#define STG_STRIDE 49152
#define SM_FULL  196608
#define SM_EMPTY (196608 + 32)
#define SMEM_TOTAL (196608 + 64)

// ---- device scratch ----
__device__ __align__(128) __nv_bfloat16 g_Ab[2][2][BQ][KP];   // ~10.5MB
__device__ __align__(128) __nv_bfloat16 g_Wb[2][NGI][KP];     // ~10.5MB
__device__ __align__(128) float         g_bias[2][NGI];
__device__ __align__(128) float         g_Hf[2][2][BQ][HQ];   // ~8.4MB
__device__ __align__(128) float         g_S[BQ][BQ];          // 4MB

// ---- asm helpers ----
#define LDSM4(R0,R1,R2,R3,ADDR) \
  asm volatile("ldmatrix.sync.aligned.m8n8.x4.shared.b16 {%0,%1,%2,%3},[%4];" \
    : "=r"(R0),"=r"(R1),"=r"(R2),"=r"(R3) : "r"(ADDR))

#define MMA16816(C,A0,A1,A2,A3,B0,B1) \
  asm volatile("mma.sync.aligned.m16n8k16.row.col.f32.bf16.bf16.f32 " \
    "{%0,%1,%2,%3},{%4,%5,%6,%7},{%8,%9},{%0,%1,%2,%3};" \
    : "+f"(C[0]),"+f"(C[1]),"+f"(C[2]),"+f"(C[3]) \
    : "r"(A0),"r"(A1),"r"(A2),"r"(A3),"r"(B0),"r"(B1))

#define CPASYNC16(DST,SRC) \
  asm volatile("cp.async.cg.shared.global [%0],[%1],16;" :: "r"(DST),"l"(SRC))

#define CPASYNC_ARRIVE(MBAR) \
  asm volatile("cp.async.mbarrier.arrive.noinc.shared::cta.b64 [%0];" :: "r"(MBAR) : "memory")

#define MBARRIER_INIT(addr, cnt) \
  asm volatile("mbarrier.init.shared.b64 [%0], %1;" :: "r"(addr), "r"(cnt) : "memory")
#define MBARRIER_INVAL(addr) \
  asm volatile("mbarrier.inval.shared.b64 [%0];" :: "r"(addr) : "memory")
#define MBARRIER_ARRIVE(addr) \
  asm volatile("mbarrier.arrive.shared::cta.b64 _, [%0];" :: "r"(addr) : "memory")

#define MBARRIER_WAIT_PARITY(addr, par) do { \
    uint32_t _m = (addr), _p = (par), _done; \
    asm volatile("{\n\t.reg .pred p;\n\tmbarrier.try_wait.parity.acquire.cta.shared::cta.b64 p, [%1], %2;\n\tselp.b32 %0,1,0,p;\n\t}" \
        : "=r"(_done) : "r"(_m), "r"(_p) : "memory"); \
    if (!_done) { \
        asm volatile("{\n\t.reg .pred P1;\n\tWL_%=:\n\tmbarrier.try_wait.parity.acquire.cta.shared::cta.b64 P1, [%0], %1, 0x989680;\n\t@P1 bra.uni WD_%=;\n\tbra.uni WL_%=;\n\tWD_%=:\n\t}" \
            :: "r"(_m), "r"(_p) : "memory"); \
    } \
} while (0)

// ---------------------------------------------------------------------------
// Pack weights. Output col n: wgrp=n>>6, c=n&63, ni=c>>3, j=c&7,
// gate=ni>>1 (0=r,1=z,2=gh_n,3=gi_n), u=((ni&1)<<3)|j, h=wgrp*16+u.
// Both k-terms hold W_hi (A carries the hi/lo split).
// ---------------------------------------------------------------------------
__global__ void pack_weights(const float* __restrict__ Wih0, const float* __restrict__ Whh0,
                             const float* __restrict__ bih0, const float* __restrict__ bhh0,
                             const float* __restrict__ Wih1, const float* __restrict__ Whh1,
                             const float* __restrict__ bih1, const float* __restrict__ bhh1) {
    const long total = 2L * NGI * KP;
    for (long idx = (long)blockIdx.x * blockDim.x + threadIdx.x; idx < total;
         idx += (long)gridDim.x * blockDim.x) {
        int g   = (int)(idx / (NGI * (long)KP));
        int rem = (int)(idx - (long)g * NGI * KP);
        int n = rem / KP;
        int k = rem - n * KP;
        int kk = (k >= KT) ? (k - KT) : k;
        int wgrp = n >> 6;
        int c = n & 63;
        int ni = c >> 3;
        int j = c & 7;
        int gate = ni >> 1;
        int u = ((ni & 1) << 3) | j;
        int h = wgrp * 16 + u;
        const float* Wih = g ? Wih1 : Wih0;
        const float* Whh = g ? Whh1 : Whh0;
        float v = 0.f;
        if (kk < HQ) {
            if (gate == 0)      v = Whh[(0 * HQ + h) * HQ + kk];
            else if (gate == 1) v = Whh[(1 * HQ + h) * HQ + kk];
            else if (gate == 2) v = Whh[(2 * HQ + h) * HQ + kk];
        } else {
            int e = kk - HQ;
            if (e < EQ) {
                if (gate == 0)      v = Wih[(0 * HQ + h) * EQ + e];
                else if (gate == 1) v = Wih[(1 * HQ + h) * EQ + e];
                else if (gate == 3) v = Wih[(2 * HQ + h) * EQ + e];
            }
        }
        g_Wb[g][n][k] = __float2bfloat16(v);
    }
    for (int idx = blockIdx.x * blockDim.x + threadIdx.x; idx < 2 * NGI;
         idx += gridDim.x * blockDim.x) {
        int g = idx / NGI;
        int n = idx - g * NGI;
        int wgrp = n >> 6;
        int c = n & 63;
        int ni = c >> 3;
        int gate = ni >> 1;
        int u = ((ni & 1) << 3) | (c & 7);
        int h = wgrp * 16 + u;
        const float* bih = g ? bih1 : bih0;
        const float* bhh = g ? bhh1 : bhh0;
        float b;
        if (gate == 0)      b = bih[h] + bhh[h];
        else if (gate == 1) b = bih[HQ + h] + bhh[HQ + h];
        else if (gate == 2) b = bhh[2 * HQ + h];
        else                b = bih[2 * HQ + h];
        g_bias[g][n] = b;
    }
}

// Init: h=0, x gather for step 0 (t = L-1). A terms: t0=hi, t1=lo.
__global__ void init_state(const int* __restrict__ tok0, const int* __restrict__ tok1,
                           const float* __restrict__ emb0, const float* __restrict__ emb1) {
    const long totalA = 2L * BQ * KP;
    for (long idx = (long)blockIdx.x * blockDim.x + threadIdx.x; idx < totalA;
         idx += (long)gridDim.x * blockDim.x) {
        int g   = (int)(idx / (BQ * (long)KP));
        int rem = (int)(idx - (long)g * BQ * KP);
        int row = rem / KP;
        int k   = rem - row * KP;
        int t  = (k >= KT) ? 1 : 0;
        int kk = k - t * KT;
        __nv_bfloat16 out = __float2bfloat16(0.f);
        if (kk >= HQ && (kk - HQ) < EQ) {
            int e = kk - HQ;
            const int*   tok = g ? tok1 : tok0;
            const float* emb = g ? emb1 : emb0;
            int ti = tok[row * LQ + (LQ - 1)];
            float v = emb[ti * EQ + e];
            __nv_bfloat16 hi = __float2bfloat16(v);
            out = t ? __float2bfloat16(v - __bfloat162float(hi)) : hi;
        }
        g_Ab[0][g][row][k] = out;
    }
    const int totalH = 2 * BQ * HQ;
    for (int idx = blockIdx.x * blockDim.x + threadIdx.x; idx < totalH;
         idx += gridDim.x * blockDim.x) {
        int g   = idx / (BQ * HQ);
        int rem = idx - g * BQ * HQ;
        g_Hf[0][g][rem / HQ][rem % HQ] = 0.f;
    }
}

// ---------------------------------------------------------------------------
// Fused GRU step. CTA tile 256x128, K'=1280, 4-stage mbarrier pipeline with
// NO block-wide barrier in the mainloop (warps skew up to 3 stages).
// grid (4,16,2) x 512 threads.
// ---------------------------------------------------------------------------
__global__ __launch_bounds__(512, 1) void gru_step(int cur, int s_next,
        const int* __restrict__ tok0, const int* __restrict__ tok1,
        const float* __restrict__ emb0, const float* __restrict__ emb1) {
    extern __shared__ char smem[];
    const uint32_t sbase = (uint32_t)__cvta_generic_to_shared(smem);
    const int g     = blockIdx.z;
    const int m0    = blockIdx.x * 256;
    const int group = blockIdx.y;
    const int n0    = group * 128;
    const int nxt   = cur ^ 1;
    const int tid   = threadIdx.x;
    const int lane  = tid & 31;
    const int warp  = tid >> 5;
    const int wm    = (warp >> 1) << 5;   // 0..224
    const int wn    = (warp & 1) << 6;    // 0 or 64

    // mbarrier init: full[s] = 512 cp.async-completions, empty[s] = 16 warp arrives
    if (tid == 0) {
#pragma unroll
        for (int s = 0; s < 4; s++) {
            MBARRIER_INIT(sbase + SM_FULL  + 8 * s, 512);
            MBARRIER_INIT(sbase + SM_EMPTY + 8 * s, 16);
        }
    }
    __syncthreads();

    const __nv_bfloat16* gA = &g_Ab[cur][g][m0][0];
    const __nv_bfloat16* gB = &g_Wb[g][n0][0];

    uint32_t aDst[4]; const __nv_bfloat16* aSrc[4];
#pragma unroll
    for (int p = 0; p < 4; p++) {
        int unit = tid + 512 * p;        // 2048 units: 256 rows x 8
        int r = unit >> 3, c = unit & 7;
        aDst[p] = (uint32_t)(r * 128 + ((c ^ (r & 7)) << 4));
        aSrc[p] = gA + r * KP + c * 8;
    }
    uint32_t bDst[2]; const __nv_bfloat16* bSrc[2];
#pragma unroll
    for (int p = 0; p < 2; p++) {
        int unit = tid + 512 * p;        // 1024 units: 128 rows x 8
        int r = unit >> 3, c = unit & 7;
        bDst[p] = (uint32_t)(r * 128 + ((c ^ (r & 7)) << 4));
        bSrc[p] = gB + r * KP + c * 8;
    }

#define STAGE_CP(BUF, KOFF) do { \
    uint32_t _aB = sbase + (uint32_t)(BUF) * STG_STRIDE; \
    uint32_t _bB = _aB + 32768; \
    int _k0 = (KOFF); \
    CPASYNC16(_aB + aDst[0], aSrc[0] + _k0); \
    CPASYNC16(_aB + aDst[1], aSrc[1] + _k0); \
    CPASYNC16(_aB + aDst[2], aSrc[2] + _k0); \
    CPASYNC16(_aB + aDst[3], aSrc[3] + _k0); \
    CPASYNC16(_bB + bDst[0], bSrc[0] + _k0); \
    CPASYNC16(_bB + bDst[1], bSrc[1] + _k0); \
    CPASYNC_ARRIVE(sbase + SM_FULL + 8 * (BUF)); \
} while (0)

    float acc[2][8][4];
#pragma unroll
    for (int mi = 0; mi < 2; mi++)
#pragma unroll
        for (int ni = 0; ni < 8; ni++)
#pragma unroll
            for (int q = 0; q < 4; q++) acc[mi][ni][q] = 0.f;

    // prologue: stage k-iters 0,1,2
#pragma unroll
    for (int i0 = 0; i0 < 3; i0++) STAGE_CP(i0, i0 * 64);

    for (int i = 0; i < NK_ITERS; i++) {
        const int buf = i & 3;
        // consumer: wait stage i data (generation i>>2)
        MBARRIER_WAIT_PARITY(sbase + SM_FULL + 8 * buf, (i >> 2) & 1);

        const uint32_t aB = sbase + (uint32_t)buf * STG_STRIDE;
        const uint32_t bB = aB + 32768;

#pragma unroll
        for (int kc = 0; kc < 4; kc++) {
            uint32_t a[2][4];
#pragma unroll
            for (int mi = 0; mi < 2; mi++) {
                int rrow = wm + mi * 16 + (lane & 15);
                int uc = kc * 2 + (lane >> 4);
                uint32_t addr = aB + (uint32_t)(rrow * 128 + ((uc ^ (rrow & 7)) << 4));
                LDSM4(a[mi][0], a[mi][1], a[mi][2], a[mi][3], addr);
            }
            uint32_t b[4][4];
#pragma unroll
            for (int j = 0; j < 4; j++) {
                int rrow = wn + 16 * j + (lane & 7) + ((lane >> 4) << 3);
                int uc = kc * 2 + ((lane >> 3) & 1);
                uint32_t addr = bB + (uint32_t)(rrow * 128 + ((uc ^ (rrow & 7)) << 4));
                LDSM4(b[j][0], b[j][1], b[j][2], b[j][3], addr);
            }
#pragma unroll
            for (int mi = 0; mi < 2; mi++)
#pragma unroll
                for (int ni = 0; ni < 8; ni++) {
                    int j = ni >> 1, hh = (ni & 1) << 1;
                    MMA16816(acc[mi][ni], a[mi][0], a[mi][1], a[mi][2], a[mi][3],
                             b[j][hh], b[j][hh + 1]);
                }
        }
        __syncwarp();
        if (lane == 0) MBARRIER_ARRIVE(sbase + SM_EMPTY + 8 * buf);

        // producer: refill buffer (i+3)&3 for stage i+3
        if (i + 3 < NK_ITERS) {
            if (i >= 1) {
                int b = (i - 1) & 3;   // == (i+3)&3
                MBARRIER_WAIT_PARITY(sbase + SM_EMPTY + 8 * b, ((i - 1) >> 2) & 1);
            }
            STAGE_CP((i + 3) & 3, (i + 3) * 64);
        }
    }

    // ---- in-register gate epilogue (no block sync needed; acc is private) ----
    const int wgrp = group * 2 + (warp & 1);          // 0..31
    const float* bias = &g_bias[g][n0 + wn];
#pragma unroll
    for (int mi = 0; mi < 2; mi++)
#pragma unroll
        for (int s = 0; s < 2; s++)
#pragma unroll
            for (int qh = 0; qh < 2; qh++) {
                const int R = m0 + wm + mi * 16 + (lane >> 2) + qh * 8;
                const int jb = (lane & 3) * 2;
                const int hb = wgrp * 16 + s * 8 + jb;   // even
                float hn2[2];
#pragma unroll
                for (int qp = 0; qp < 2; qp++) {
                    const int q = qh * 2 + qp;
                    const int j = jb + qp;
                    float rp = acc[mi][0 + s][q] + bias[(0 + s) * 8 + j];
                    float zp = acc[mi][2 + s][q] + bias[(2 + s) * 8 + j];
                    float gn = acc[mi][4 + s][q] + bias[(4 + s) * 8 + j];
                    float gi = acc[mi][6 + s][q] + bias[(6 + s) * 8 + j];
                    float rr = 1.f / (1.f + __expf(-rp));
                    float zz = 1.f / (1.f + __expf(-zp));
                    float pre = gi + rr * gn;
                    float ex = __expf(-2.f * fabsf(pre));
                    float nn = copysignf((1.f - ex) / (1.f + ex), pre);
                    float ho = g_Hf[cur][g][R][hb + qp];
                    hn2[qp] = (1.f - zz) * nn + zz * ho;
                }
                g_Hf[nxt][g][R][hb]     = hn2[0];
                g_Hf[nxt][g][R][hb + 1] = hn2[1];
                __nv_bfloat16 h0 = __float2bfloat16(hn2[0]);
                __nv_bfloat16 h1 = __float2bfloat16(hn2[1]);
                __nv_bfloat162 hi2; hi2.x = h0; hi2.y = h1;
                __nv_bfloat162 lo2;
                lo2.x = __float2bfloat16(hn2[0] - __bfloat162float(h0));
                lo2.y = __float2bfloat16(hn2[1] - __bfloat162float(h1));
                *(__nv_bfloat162*)&g_Ab[nxt][g][R][hb]      = hi2;
                *(__nv_bfloat162*)&g_Ab[nxt][g][R][KT + hb] = lo2;
            }

    // embedding gather for next step: this CTA handles 16 of its 256 rows
    if (s_next < LQ) {
        const int*   tok = g ? tok1 : tok0;
        const float* emb = g ? emb1 : emb0;
        int rbase = m0 + group * 16;
        for (int idx = tid; idx < 16 * EQ; idx += 512) {
            int r = idx / EQ, e = idx - r * EQ;
            int R = rbase + r;
            int ti = tok[R * LQ + (LQ - 1 - s_next)];
            float v = emb[ti * EQ + e];
            __nv_bfloat16 hi = __float2bfloat16(v);
            g_Ab[nxt][g][R][HQ + e]      = hi;
            g_Ab[nxt][g][R][KT + HQ + e] = __float2bfloat16(v - __bfloat162float(hi));
        }
    }

    __syncthreads();
    if (tid == 0) {
#pragma unroll
        for (int s = 0; s < 4; s++) {
            MBARRIER_INVAL(sbase + SM_FULL  + 8 * s);
            MBARRIER_INVAL(sbase + SM_EMPTY + 8 * s);
        }
    }
}

// ---------------------------------------------------------------------------
// S = hc @ hr^T (fp32, K=512) + row softmax
// ---------------------------------------------------------------------------
__global__ __launch_bounds__(256) void score_gemm() {
    const int bm = blockIdx.y;
    const int bn = blockIdx.x;
    __shared__ float As[16][68];
    __shared__ float Bs[16][68];
    const int tid = threadIdx.x;
    const int tx = tid & 15;
    const int ty = tid >> 4;

    float acc[4][4];
#pragma unroll
    for (int i = 0; i < 4; i++)
#pragma unroll
        for (int j = 0; j < 4; j++) acc[i][j] = 0.f;

    const float* Abase = &g_Hf[0][0][bm * 64][0];
    const float* Bbase = &g_Hf[0][1][bn * 64][0];

    for (int k0 = 0; k0 < HQ; k0 += 16) {
#pragma unroll
        for (int i = 0; i < 4; i++) {
            int e = tid + 256 * i;
            int m = e >> 4;
            int k = e & 15;
            As[k][m] = Abase[m * HQ + k0 + k];
            Bs[k][m] = Bbase[m * HQ + k0 + k];
        }
        __syncthreads();
#pragma unroll
        for (int kk = 0; kk < 16; kk++) {
            float4 a4 = *(const float4*)&As[kk][ty * 4];
            float4 b4 = *(const float4*)&Bs[kk][tx * 4];
            float av[4] = {a4.x, a4.y, a4.z, a4.w};
            float bv[4] = {b4.x, b4.y, b4.z, b4.w};
#pragma unroll
            for (int i = 0; i < 4; i++)
#pragma unroll
                for (int j = 0; j < 4; j++) acc[i][j] += av[i] * bv[j];
        }
        __syncthreads();
    }
    const int row = bm * 64 + ty * 4;
    const int col = bn * 64 + tx * 4;
#pragma unroll
    for (int i = 0; i < 4; i++)
#pragma unroll
        for (int j = 0; j < 4; j++) g_S[row + i][col + j] = acc[i][j];
}

__global__ void softmax_rows(float* __restrict__ out) {
    const int row = blockIdx.x;
    __shared__ float red[256];
    const float* Srow = g_S[row];

    float m = -INFINITY;
    for (int j = threadIdx.x; j < BQ; j += 256) m = fmaxf(m, Srow[j]);
    red[threadIdx.x] = m;
    __syncthreads();
    for (int off = 128; off; off >>= 1) {
        if (threadIdx.x < off) red[threadIdx.x] = fmaxf(red[threadIdx.x], red[threadIdx.x + off]);
        __syncthreads();
    }
    m = red[0];
    __syncthreads();

    float sum = 0.f;
    for (int j = threadIdx.x; j < BQ; j += 256) sum += expf(Srow[j] - m);
    red[threadIdx.x] = sum;
    __syncthreads();
    for (int off = 128; off; off >>= 1) {
        if (threadIdx.x < off) red[threadIdx.x] += red[threadIdx.x + off];
        __syncthreads();
    }
    sum = red[0];

    float inv = 1.f / sum;
    for (int j = threadIdx.x; j < BQ; j += 256) out[row * BQ + j] = expf(Srow[j] - m) * inv;
}

// ---------------------------------------------------------------------------
extern "C" void kernel_launch(void* const* d_in, const int* in_sizes, int n_in,
                              void* d_out, int out_size) {
    const int*   ctx     = (const int*)  d_in[0];
    const int*   rep     = (const int*)  d_in[1];
    const float* ctx_emb = (const float*)d_in[2];
    const float* ctx_Wih = (const float*)d_in[3];
    const float* ctx_Whh = (const float*)d_in[4];
    const float* ctx_bih = (const float*)d_in[5];
    const float* ctx_bhh = (const float*)d_in[6];
    const float* rep_emb = (const float*)d_in[7];
    const float* rep_Wih = (const float*)d_in[8];
    const float* rep_Whh = (const float*)d_in[9];
    const float* rep_bih = (const float*)d_in[10];
    const float* rep_bhh = (const float*)d_in[11];

    cudaFuncSetAttribute(gru_step, cudaFuncAttributeMaxDynamicSharedMemorySize, SMEM_TOTAL);

    pack_weights<<<4096, 256>>>(ctx_Wih, ctx_Whh, ctx_bih, ctx_bhh,
                                rep_Wih, rep_Whh, rep_bih, rep_bhh);
    init_state<<<4096, 256>>>(ctx, rep, ctx_emb, rep_emb);

    for (int s = 0; s < LQ; s++) {
        int cur = s & 1;
        gru_step<<<dim3(4, 16, 2), 512, SMEM_TOTAL>>>(cur, s + 1, ctx, rep, ctx_emb, rep_emb);
    }

    score_gemm<<<dim3(16, 16), 256>>>();
    softmax_rows<<<BQ, 256>>>((float*)d_out);
}